// round 11
// baseline (speedup 1.0000x reference)
#include <cuda_runtime.h>
#include <math.h>

// Problem dims (fixed by the dataset)
#define NB 4
#define CC 256
#define TT 16
#define HH 56
#define WW 56
#define KK 16
#define TP 8
#define HP 28
#define WP 28
#define PLANE (TT*HH*WW)        // 50176, channel stride in vw
#define OPLANE (TP*HP*WP)       // 6272, channel stride in out
#define SPLANE (HH*WW)          // 3136 spatial points per (n,t)

// Scratch: exp map, [N, T, H, W]
__device__ float g_emap[NB * TT * HH * WW];

__device__ __forceinline__ unsigned long long fma2(unsigned long long a,
                                                   unsigned long long b,
                                                   unsigned long long c) {
    unsigned long long d;
    asm("fma.rn.f32x2 %0, %1, %2, %3;" : "=l"(d) : "l"(a), "l"(b), "l"(c));
    return d;
}

__device__ __forceinline__ float lo32(unsigned long long v) {
    return __uint_as_float((unsigned)v);
}
__device__ __forceinline__ float hi32(unsigned long long v) {
    return __uint_as_float((unsigned)(v >> 32));
}

// ---------------------------------------------------------------------------
// Kernel 1 (R7 structure — best measured emap): half-warp K-split + two
// pair streams per warp, c-step 8 (16 outstanding LDG.64/lane), (224,3).
// Per-launch batch index n passed as a parameter; grid (7, 16, 1).
// ---------------------------------------------------------------------------
__global__ __launch_bounds__(224, 3) void emap_kernel(const float* __restrict__ vw,
                                                      const float* __restrict__ wmat,
                                                      int n) {
    __shared__ unsigned long long wsp[CC * KK];  // [c][k], each {s,s} packed

    const int t = blockIdx.y;
    const int tid = threadIdx.y * 32 + threadIdx.x;

    // Load weights for this n into smem, duplicated into both f32x2 halves.
    const float* wn = wmat + (size_t)n * KK * CC;   // layout [k][c]
    for (int j = tid; j < KK * CC; j += 224) {
        int k = j >> 8;        // j = k*256 + c
        int c = j & 255;
        unsigned int si = __float_as_uint(wn[j]);
        wsp[c * KK + k] = ((unsigned long long)si << 32) | si;
    }
    __syncthreads();

    const int lane  = threadIdx.x;
    const int khalf = lane >> 4;                       // 0 or 1
    const int li    = lane & 15;
    const int wg    = blockIdx.x * 7 + threadIdx.y;    // 0..48
    const int pairA = wg * 32 + li;                    // pairs 0..15 of strip

    size_t baseA = ((size_t)n * CC * TT + t) * SPLANE + 2 * pairA;
    const unsigned long long* srcA = (const unsigned long long*)(vw + baseA);
    const unsigned long long* srcB = srcA + 16;   // +16 pairs = +32 floats

    unsigned long long accA[8], accB[8];
#pragma unroll
    for (int k = 0; k < 8; k++) { accA[k] = 0ull; accB[k] = 0ull; }

    const ulonglong2* wv = (const ulonglong2*)wsp;

    for (int c0 = 0; c0 < CC; c0 += 8) {
        unsigned long long xA[8], xB[8];
#pragma unroll
        for (int u = 0; u < 8; u++) {
            xA[u] = __ldg(srcA + (size_t)u * (PLANE / 2));
            xB[u] = __ldg(srcB + (size_t)u * (PLANE / 2));
        }
        srcA += 8 * (size_t)(PLANE / 2);
        srcB += 8 * (size_t)(PLANE / 2);
#pragma unroll
        for (int u = 0; u < 8; u++) {
            ulonglong2 wp0 = wv[(c0 + u) * (KK / 2) + khalf * 4 + 0];
            ulonglong2 wp1 = wv[(c0 + u) * (KK / 2) + khalf * 4 + 1];
            accA[0] = fma2(wp0.x, xA[u], accA[0]);
            accA[1] = fma2(wp0.y, xA[u], accA[1]);
            accB[0] = fma2(wp0.x, xB[u], accB[0]);
            accB[1] = fma2(wp0.y, xB[u], accB[1]);
            accA[2] = fma2(wp1.x, xA[u], accA[2]);
            accA[3] = fma2(wp1.y, xA[u], accA[3]);
            accB[2] = fma2(wp1.x, xB[u], accB[2]);
            accB[3] = fma2(wp1.y, xB[u], accB[3]);
            ulonglong2 wp2 = wv[(c0 + u) * (KK / 2) + khalf * 4 + 2];
            ulonglong2 wp3 = wv[(c0 + u) * (KK / 2) + khalf * 4 + 3];
            accA[4] = fma2(wp2.x, xA[u], accA[4]);
            accA[5] = fma2(wp2.y, xA[u], accA[5]);
            accB[4] = fma2(wp2.x, xB[u], accB[4]);
            accB[5] = fma2(wp2.y, xB[u], accB[5]);
            accA[6] = fma2(wp3.x, xA[u], accA[6]);
            accA[7] = fma2(wp3.y, xA[u], accA[7]);
            accB[6] = fma2(wp3.x, xB[u], accB[6]);
            accB[7] = fma2(wp3.y, xB[u], accB[7]);
        }
    }

    float mA0 = -3.4e38f, mA1 = -3.4e38f, mB0 = -3.4e38f, mB1 = -3.4e38f;
#pragma unroll
    for (int k = 0; k < 8; k++) {
        mA0 = fmaxf(mA0, lo32(accA[k]));
        mA1 = fmaxf(mA1, hi32(accA[k]));
        mB0 = fmaxf(mB0, lo32(accB[k]));
        mB1 = fmaxf(mB1, hi32(accB[k]));
    }
    mA0 = fmaxf(mA0, __shfl_xor_sync(0xffffffffu, mA0, 16));
    mA1 = fmaxf(mA1, __shfl_xor_sync(0xffffffffu, mA1, 16));
    mB0 = fmaxf(mB0, __shfl_xor_sync(0xffffffffu, mB0, 16));
    mB1 = fmaxf(mB1, __shfl_xor_sync(0xffffffffu, mB1, 16));

    if (khalf == 0) {
        size_t eidx = ((size_t)n * TT + t) * SPLANE + 2 * pairA;
        *(float2*)(g_emap + eidx) =
            make_float2(expf(mA0 * 0.0625f), expf(mA1 * 0.0625f));
        *(float2*)(g_emap + eidx + 32) =
            make_float2(expf(mB0 * 0.0625f), expf(mB1 * 0.0625f));
    }
}

// ---------------------------------------------------------------------------
// Kernel 2 (R8 structure — best measured pool): lane owns output pair
// (2w2, 2w2+1); one LDG.128 per row per channel; the w-1 corner term comes
// from the left lane via one shfl_up per channel after the r-loop.
// Per-launch batch index n passed as a parameter; grid (HP, TP, 2).
// ---------------------------------------------------------------------------
__global__ __launch_bounds__(256, 4) void pool_kernel(const float* __restrict__ vw,
                                                      float* __restrict__ out,
                                                      int n) {
    const int chalf = blockIdx.z;
    const int tp = blockIdx.y;
    const int hp = blockIdx.x;
    const int tid = threadIdx.y * 32 + threadIdx.x;

    __shared__ float4 wpk[9 * 14];   // {e[4w2], e[4w2+1], e[4w2+2], e[4w2+3]} per (r,w2)
    __shared__ float  wem[9 * 14];   // e[4w2-1]  (denominator only)
    __shared__ float  wrd[14 * 2];   // 1/denominator for outputs (2w2, 2w2+1)

    // Fill window-weight tables (126 items).
    if (tid < 126) {
        const int r  = tid / 14;
        const int w2 = tid - r * 14;
        const int dt = r / 3, dh = r - dt * 3;
        const int t = 2 * tp - 1 + dt;
        const int h = 2 * hp - 1 + dh;
        const bool rv = (t >= 0) && (h >= 0);
        const int tc = t > 0 ? t : 0;
        const int hc = h > 0 ? h : 0;
        const float* ep = g_emap + ((size_t)n * TT + tc) * SPLANE + (size_t)hc * WW;
        const int wb = 4 * w2;
        float em1 = (rv && wb > 0) ? ep[wb - 1] : 0.f;
        float e0 = rv ? ep[wb + 0] : 0.f;
        float e1 = rv ? ep[wb + 1] : 0.f;
        float e2 = rv ? ep[wb + 2] : 0.f;
        float e3 = rv ? ep[wb + 3] : 0.f;
        wpk[tid] = make_float4(e0, e1, e2, e3);
        wem[tid] = em1;
    }
    __syncthreads();
    if (tid < 28) {
        const int w2i = tid % 14;
        const int sel = tid / 14;
        float s = 0.f;
#pragma unroll
        for (int r = 0; r < 9; r++) {
            float4 f = wpk[r * 14 + w2i];
            s += sel ? (f.y + f.z + f.w) : (wem[r * 14 + w2i] + f.x + f.y);
        }
        wrd[w2i * 2 + sel] = 1.0f / s;
    }
    __syncthreads();

    const int lane = threadIdx.x;
    const int w2   = (lane & 15) < 14 ? (lane & 15) : 13;  // clamp
    const int csel = lane >> 4;                            // channel select 0/1
    const bool act = (lane & 15) < 14;

    const float rden0 = wrd[w2 * 2 + 0];
    const float rden1 = wrd[w2 * 2 + 1];

    int rowoff[9];
#pragma unroll
    for (int r = 0; r < 9; r++) {
        const int dt = r / 3, dh = r - dt * 3;
        const int t = 2 * tp - 1 + dt;
        const int h = 2 * hp - 1 + dh;
        const int tc = t > 0 ? t : 0;
        const int hc = h > 0 ? h : 0;
        rowoff[r] = (tc * HH + hc) * WW;
    }

    const float* basep = vw + (size_t)n * CC * PLANE + 4 * w2;
    float* outbase = out + (((size_t)n * CC * TP + tp) * HP + hp) * WP + 2 * w2;

    const int cbeg = chalf * (CC / 2);
    const ulonglong2* wpk2 = (const ulonglong2*)wpk;

    // 4 channels per warp-iteration: this lane handles cA=c0+2*csel, cB=cA+1.
    for (int c0 = cbeg + threadIdx.y * 4; c0 < cbeg + CC / 2; c0 += 32) {
        const int cA = c0 + 2 * csel;
        const float* pA = basep + (size_t)cA * PLANE;
        const float* pB = pA + PLANE;
        unsigned long long a0A = 0ull, a1A = 0ull, a0B = 0ull, a1B = 0ull;
        float sxA = 0.f, spA = 0.f, sxB = 0.f, spB = 0.f;
#pragma unroll
        for (int r = 0; r < 9; r++) {
            ulonglong2 xA = __ldg((const ulonglong2*)(pA + rowoff[r]));
            ulonglong2 xB = __ldg((const ulonglong2*)(pB + rowoff[r]));
            ulonglong2 wpr = wpk2[r * 14 + w2];   // .x = (e0,e1), .y = (e2,e3)
            a0A = fma2(wpr.x, xA.x, a0A);
            a1A = fma2(wpr.y, xA.y, a1A);
            a0B = fma2(wpr.x, xB.x, a0B);
            a1B = fma2(wpr.y, xB.y, a1B);
            sxA = fmaf(hi32(wpr.x), hi32(xA.x), sxA);   // e1*v1 -> own out1
            spA = fmaf(hi32(wpr.y), hi32(xA.y), spA);   // e3*v3 -> right nbr out0
            sxB = fmaf(hi32(wpr.x), hi32(xB.x), sxB);
            spB = fmaf(hi32(wpr.y), hi32(xB.y), spB);
        }
        float spAm = __shfl_up_sync(0xffffffffu, spA, 1);
        float spBm = __shfl_up_sync(0xffffffffu, spB, 1);
        if ((lane & 15) == 0) { spAm = 0.f; spBm = 0.f; }
        if (act) {
            float2 oA = make_float2((lo32(a0A) + hi32(a0A) + spAm) * rden0,
                                    (lo32(a1A) + hi32(a1A) + sxA) * rden1);
            float2 oB = make_float2((lo32(a0B) + hi32(a0B) + spBm) * rden0,
                                    (lo32(a1B) + hi32(a1B) + sxB) * rden1);
            *(float2*)(outbase + (size_t)cA * OPLANE) = oA;
            *(float2*)(outbase + (size_t)(cA + 1) * OPLANE) = oB;
        }
    }
}

// ---------------------------------------------------------------------------
// Pipelined launch: emap(n) on the caller's (capturing) stream, pool(n) on a
// side stream gated by an event recorded after emap(n). Fork-join via events
// is graph-capture legal: the side stream is pulled into capture by
// cudaStreamWaitEvent on an event recorded in the capturing stream, and
// rejoined before return. Streams/events are created fresh each call (the
// harness calls kernel_launch twice: correctness + capture) and intentionally
// not destroyed (cannot destroy while referenced by an active capture).
// No device memory is allocated; no syncs are issued.
// ---------------------------------------------------------------------------
extern "C" void kernel_launch(void* const* d_in, const int* in_sizes, int n_in,
                              void* d_out, int out_size) {
    const float* a0 = (const float*)d_in[0];
    const float* a1 = (const float*)d_in[1];
    // vw is the big tensor (51,380,224 elems); w is 16,384 elems.
    const float* vw   = (in_sizes[0] > in_sizes[1]) ? a0 : a1;
    const float* wmat = (in_sizes[0] > in_sizes[1]) ? a1 : a0;
    float* out = (float*)d_out;

    cudaStream_t s2;
    cudaStreamCreateWithFlags(&s2, cudaStreamNonBlocking);

    cudaEvent_t evFork, evE[NB], evJoin;
    cudaEventCreateWithFlags(&evFork, cudaEventDisableTiming);
    cudaEventCreateWithFlags(&evJoin, cudaEventDisableTiming);
    for (int n = 0; n < NB; n++)
        cudaEventCreateWithFlags(&evE[n], cudaEventDisableTiming);

    // Fork: bring s2 into the capture (and order it after prior work on 0).
    cudaEventRecord(evFork, 0);
    cudaStreamWaitEvent(s2, evFork, 0);

    for (int n = 0; n < NB; n++) {
        emap_kernel<<<dim3(7, TT, 1), dim3(32, 7), 0, 0>>>(vw, wmat, n);
        cudaEventRecord(evE[n], 0);
        cudaStreamWaitEvent(s2, evE[n], 0);
        pool_kernel<<<dim3(HP, TP, 2), dim3(32, 8), 0, s2>>>(vw, out, n);
    }

    // Join: stream 0 waits for all pool work before kernel_launch "returns".
    cudaEventRecord(evJoin, s2);
    cudaStreamWaitEvent(0, evJoin, 0);
}

// round 12
// speedup vs baseline: 2.4693x; 2.4693x over previous
#include <cuda_runtime.h>
#include <math.h>

// Problem dims (fixed by the dataset)
#define NB 4
#define CC 256
#define TT 16
#define HH 56
#define WW 56
#define KK 16
#define TP 8
#define HP 28
#define WP 28
#define PLANE (TT*HH*WW)        // 50176, channel stride in vw
#define OPLANE (TP*HP*WP)       // 6272, channel stride in out
#define SPLANE (HH*WW)          // 3136 spatial points per (n,t)
#define PL2 (PLANE/2)           // channel stride in 8-byte units

// Scratch: exp map, [N, T, H, W]
__device__ float g_emap[NB * TT * HH * WW];

__device__ __forceinline__ unsigned long long fma2(unsigned long long a,
                                                   unsigned long long b,
                                                   unsigned long long c) {
    unsigned long long d;
    asm("fma.rn.f32x2 %0, %1, %2, %3;" : "=l"(d) : "l"(a), "l"(b), "l"(c));
    return d;
}

__device__ __forceinline__ float lo32(unsigned long long v) {
    return __uint_as_float((unsigned)v);
}
__device__ __forceinline__ float hi32(unsigned long long v) {
    return __uint_as_float((unsigned)(v >> 32));
}

// ---------------------------------------------------------------------------
// Kernel 1: emap[n,t,h,w] = exp( max_k( sum_c w[n,k,c]*vw[n,c,t,h,w] ) / 16 )
// Half-warp K-split + two pair streams per warp (R7 body), now DOUBLE
// BUFFERED: the next 4-channel batch's 8 LDG.64 are issued before consuming
// the current batch, so ~8 loads/warp stay outstanding continuously.
// Little's law: 21 warps/SM x 8 x 256B / 577cyc ~ 74 B/cyc/SM >> DRAM need,
// turning the kernel from MLP-limited (3.6 TB/s) to DRAM/FMA-bound.
// acc 32 + buffers 32 + misc ~ 78 regs -> fits (224,3) without spills.
// grid (7,16,4), block (32,7).
// ---------------------------------------------------------------------------
__global__ __launch_bounds__(224, 3) void emap_kernel(const float* __restrict__ vw,
                                                      const float* __restrict__ wmat) {
    __shared__ unsigned long long wsp[CC * KK];  // [c][k], each {s,s} packed

    const int n = blockIdx.z;
    const int t = blockIdx.y;
    const int tid = threadIdx.y * 32 + threadIdx.x;

    // Load weights for this n into smem, duplicated into both f32x2 halves.
    const float* wn = wmat + (size_t)n * KK * CC;   // layout [k][c]
    for (int j = tid; j < KK * CC; j += 224) {
        int k = j >> 8;        // j = k*256 + c
        int c = j & 255;
        unsigned int si = __float_as_uint(wn[j]);
        wsp[c * KK + k] = ((unsigned long long)si << 32) | si;
    }
    __syncthreads();

    const int lane  = threadIdx.x;
    const int khalf = lane >> 4;                       // 0 or 1
    const int li    = lane & 15;
    const int wg    = blockIdx.x * 7 + threadIdx.y;    // 0..48
    const int pairA = wg * 32 + li;                    // pairs 0..15 of strip

    size_t baseA = ((size_t)n * CC * TT + t) * SPLANE + 2 * pairA;
    const unsigned long long* srcA = (const unsigned long long*)(vw + baseA);
    const unsigned long long* srcB = srcA + 16;   // +16 pairs = +32 floats

    unsigned long long accA[8], accB[8];
#pragma unroll
    for (int k = 0; k < 8; k++) { accA[k] = 0ull; accB[k] = 0ull; }

    const ulonglong2* wv = (const ulonglong2*)wsp;

    // Double buffers: x[buf][stream 0=A,1=B][u]
    unsigned long long x0A[4], x0B[4], x1A[4], x1B[4];

    // Prologue: buf0 <- channels 0..3
#pragma unroll
    for (int u = 0; u < 4; u++) {
        x0A[u] = __ldg(srcA + (size_t)u * PL2);
        x0B[u] = __ldg(srcB + (size_t)u * PL2);
    }

    // Consume a 4-channel batch held in (bA,bB) with weights at base channel cb.
#define CONSUME(bA, bB, cb)                                                    \
    do {                                                                       \
        _Pragma("unroll")                                                      \
        for (int u = 0; u < 4; u++) {                                          \
            ulonglong2 wp0 = wv[((cb) + u) * (KK / 2) + khalf * 4 + 0];        \
            ulonglong2 wp1 = wv[((cb) + u) * (KK / 2) + khalf * 4 + 1];        \
            accA[0] = fma2(wp0.x, bA[u], accA[0]);                             \
            accA[1] = fma2(wp0.y, bA[u], accA[1]);                             \
            accB[0] = fma2(wp0.x, bB[u], accB[0]);                             \
            accB[1] = fma2(wp0.y, bB[u], accB[1]);                             \
            accA[2] = fma2(wp1.x, bA[u], accA[2]);                             \
            accA[3] = fma2(wp1.y, bA[u], accA[3]);                             \
            accB[2] = fma2(wp1.x, bB[u], accB[2]);                             \
            accB[3] = fma2(wp1.y, bB[u], accB[3]);                             \
            ulonglong2 wp2 = wv[((cb) + u) * (KK / 2) + khalf * 4 + 2];        \
            ulonglong2 wp3 = wv[((cb) + u) * (KK / 2) + khalf * 4 + 3];        \
            accA[4] = fma2(wp2.x, bA[u], accA[4]);                             \
            accA[5] = fma2(wp2.y, bA[u], accA[5]);                             \
            accB[4] = fma2(wp2.x, bB[u], accB[4]);                             \
            accB[5] = fma2(wp2.y, bB[u], accB[5]);                             \
            accA[6] = fma2(wp3.x, bA[u], accA[6]);                             \
            accA[7] = fma2(wp3.y, bA[u], accA[7]);                             \
            accB[6] = fma2(wp3.x, bB[u], accB[6]);                             \
            accB[7] = fma2(wp3.y, bB[u], accB[7]);                             \
        }                                                                      \
    } while (0)

#define LOADBUF(bA, bB, cb)                                                    \
    do {                                                                       \
        _Pragma("unroll")                                                      \
        for (int u = 0; u < 4; u++) {                                          \
            bA[u] = __ldg(srcA + (size_t)((cb) + u) * PL2);                    \
            bB[u] = __ldg(srcB + (size_t)((cb) + u) * PL2);                    \
        }                                                                      \
    } while (0)

    for (int c0 = 0; c0 < CC; c0 += 8) {
        const int n1 = c0 + 4;                        // <= 252 always
        LOADBUF(x1A, x1B, n1);                        // prefetch next batch
        CONSUME(x0A, x0B, c0);                        // consume current
        const int n2 = (c0 + 8 < CC) ? (c0 + 8) : 248;  // clamp (tail reload)
        LOADBUF(x0A, x0B, n2);
        CONSUME(x1A, x1B, n1);
    }
#undef CONSUME
#undef LOADBUF

    float mA0 = -3.4e38f, mA1 = -3.4e38f, mB0 = -3.4e38f, mB1 = -3.4e38f;
#pragma unroll
    for (int k = 0; k < 8; k++) {
        mA0 = fmaxf(mA0, lo32(accA[k]));
        mA1 = fmaxf(mA1, hi32(accA[k]));
        mB0 = fmaxf(mB0, lo32(accB[k]));
        mB1 = fmaxf(mB1, hi32(accB[k]));
    }
    mA0 = fmaxf(mA0, __shfl_xor_sync(0xffffffffu, mA0, 16));
    mA1 = fmaxf(mA1, __shfl_xor_sync(0xffffffffu, mA1, 16));
    mB0 = fmaxf(mB0, __shfl_xor_sync(0xffffffffu, mB0, 16));
    mB1 = fmaxf(mB1, __shfl_xor_sync(0xffffffffu, mB1, 16));

    if (khalf == 0) {
        size_t eidx = ((size_t)n * TT + t) * SPLANE + 2 * pairA;
        *(float2*)(g_emap + eidx) =
            make_float2(expf(mA0 * 0.0625f), expf(mA1 * 0.0625f));
        *(float2*)(g_emap + eidx + 32) =
            make_float2(expf(mB0 * 0.0625f), expf(mB1 * 0.0625f));
    }
}

// ---------------------------------------------------------------------------
// Kernel 2 (R8 structure — best measured pool, near DRAM roofline): lane owns
// output pair (2w2, 2w2+1); one LDG.128 per row per channel; the w-1 corner
// term comes from the left lane via one shfl_up per channel after the r-loop.
// grid (HP, TP, NB*2), block (32,8).
// ---------------------------------------------------------------------------
__global__ __launch_bounds__(256, 4) void pool_kernel(const float* __restrict__ vw,
                                                      float* __restrict__ out) {
    const int n     = blockIdx.z >> 1;
    const int chalf = blockIdx.z & 1;
    const int tp = blockIdx.y;
    const int hp = blockIdx.x;
    const int tid = threadIdx.y * 32 + threadIdx.x;

    __shared__ float4 wpk[9 * 14];   // {e[4w2], e[4w2+1], e[4w2+2], e[4w2+3]} per (r,w2)
    __shared__ float  wem[9 * 14];   // e[4w2-1]  (denominator only)
    __shared__ float  wrd[14 * 2];   // 1/denominator for outputs (2w2, 2w2+1)

    // Fill window-weight tables (126 items).
    if (tid < 126) {
        const int r  = tid / 14;
        const int w2 = tid - r * 14;
        const int dt = r / 3, dh = r - dt * 3;
        const int t = 2 * tp - 1 + dt;
        const int h = 2 * hp - 1 + dh;
        const bool rv = (t >= 0) && (h >= 0);
        const int tc = t > 0 ? t : 0;
        const int hc = h > 0 ? h : 0;
        const float* ep = g_emap + ((size_t)n * TT + tc) * SPLANE + (size_t)hc * WW;
        const int wb = 4 * w2;
        float em1 = (rv && wb > 0) ? ep[wb - 1] : 0.f;
        float e0 = rv ? ep[wb + 0] : 0.f;
        float e1 = rv ? ep[wb + 1] : 0.f;
        float e2 = rv ? ep[wb + 2] : 0.f;
        float e3 = rv ? ep[wb + 3] : 0.f;
        wpk[tid] = make_float4(e0, e1, e2, e3);
        wem[tid] = em1;
    }
    __syncthreads();
    if (tid < 28) {
        const int w2i = tid % 14;
        const int sel = tid / 14;
        float s = 0.f;
#pragma unroll
        for (int r = 0; r < 9; r++) {
            float4 f = wpk[r * 14 + w2i];
            s += sel ? (f.y + f.z + f.w) : (wem[r * 14 + w2i] + f.x + f.y);
        }
        wrd[w2i * 2 + sel] = 1.0f / s;
    }
    __syncthreads();

    const int lane = threadIdx.x;
    const int w2   = (lane & 15) < 14 ? (lane & 15) : 13;  // clamp
    const int csel = lane >> 4;                            // channel select 0/1
    const bool act = (lane & 15) < 14;

    const float rden0 = wrd[w2 * 2 + 0];
    const float rden1 = wrd[w2 * 2 + 1];

    int rowoff[9];
#pragma unroll
    for (int r = 0; r < 9; r++) {
        const int dt = r / 3, dh = r - dt * 3;
        const int t = 2 * tp - 1 + dt;
        const int h = 2 * hp - 1 + dh;
        const int tc = t > 0 ? t : 0;
        const int hc = h > 0 ? h : 0;
        rowoff[r] = (tc * HH + hc) * WW;
    }

    const float* basep = vw + (size_t)n * CC * PLANE + 4 * w2;
    float* outbase = out + (((size_t)n * CC * TP + tp) * HP + hp) * WP + 2 * w2;

    const int cbeg = chalf * (CC / 2);
    const ulonglong2* wpk2 = (const ulonglong2*)wpk;

    // 4 channels per warp-iteration: this lane handles cA=c0+2*csel, cB=cA+1.
    for (int c0 = cbeg + threadIdx.y * 4; c0 < cbeg + CC / 2; c0 += 32) {
        const int cA = c0 + 2 * csel;
        const float* pA = basep + (size_t)cA * PLANE;
        const float* pB = pA + PLANE;
        unsigned long long a0A = 0ull, a1A = 0ull, a0B = 0ull, a1B = 0ull;
        float sxA = 0.f, spA = 0.f, sxB = 0.f, spB = 0.f;
#pragma unroll
        for (int r = 0; r < 9; r++) {
            ulonglong2 xA = __ldg((const ulonglong2*)(pA + rowoff[r]));
            ulonglong2 xB = __ldg((const ulonglong2*)(pB + rowoff[r]));
            ulonglong2 wpr = wpk2[r * 14 + w2];   // .x = (e0,e1), .y = (e2,e3)
            a0A = fma2(wpr.x, xA.x, a0A);
            a1A = fma2(wpr.y, xA.y, a1A);
            a0B = fma2(wpr.x, xB.x, a0B);
            a1B = fma2(wpr.y, xB.y, a1B);
            sxA = fmaf(hi32(wpr.x), hi32(xA.x), sxA);   // e1*v1 -> own out1
            spA = fmaf(hi32(wpr.y), hi32(xA.y), spA);   // e3*v3 -> right nbr out0
            sxB = fmaf(hi32(wpr.x), hi32(xB.x), sxB);
            spB = fmaf(hi32(wpr.y), hi32(xB.y), spB);
        }
        float spAm = __shfl_up_sync(0xffffffffu, spA, 1);
        float spBm = __shfl_up_sync(0xffffffffu, spB, 1);
        if ((lane & 15) == 0) { spAm = 0.f; spBm = 0.f; }
        if (act) {
            float2 oA = make_float2((lo32(a0A) + hi32(a0A) + spAm) * rden0,
                                    (lo32(a1A) + hi32(a1A) + sxA) * rden1);
            float2 oB = make_float2((lo32(a0B) + hi32(a0B) + spBm) * rden0,
                                    (lo32(a1B) + hi32(a1B) + sxB) * rden1);
            *(float2*)(outbase + (size_t)cA * OPLANE) = oA;
            *(float2*)(outbase + (size_t)(cA + 1) * OPLANE) = oB;
        }
    }
}

extern "C" void kernel_launch(void* const* d_in, const int* in_sizes, int n_in,
                              void* d_out, int out_size) {
    const float* a0 = (const float*)d_in[0];
    const float* a1 = (const float*)d_in[1];
    // vw is the big tensor (51,380,224 elems); w is 16,384 elems.
    const float* vw   = (in_sizes[0] > in_sizes[1]) ? a0 : a1;
    const float* wmat = (in_sizes[0] > in_sizes[1]) ? a1 : a0;
    float* out = (float*)d_out;

    emap_kernel<<<dim3(7, TT, NB), dim3(32, 7)>>>(vw, wmat);
    pool_kernel<<<dim3(HP, TP, NB * 2), dim3(32, 8)>>>(vw, out);
}